// round 15
// baseline (speedup 1.0000x reference)
#include <cuda_runtime.h>
#include <cuda_fp16.h>
#include <cstdint>

#define N_NODES 30000
#define N_PAD   30080           // 235 * 128
#define N_EDGES 240000
#define DM 256
#define QKVW 768
#define NGRAPH 64
#define NLAYER 3
#define SCAN_B  30              // ceil(30000/1024)

// GEMM smem layout (fp16 elems per stage): A 128x72 (64 data + 8 pad), B 64x136
#define ASTRIDE 72
#define BSTRIDE 136
#define OFF_B   9216
#define STAGE_E 17920           // elems per stage (35840 B); 3 stages = 107520 B

// ---------------- scratch ----------------
__device__ __align__(128) float  g_q[N_NODES * DM];        // fp32 q
__device__ __align__(128) __half g_kv[N_NODES * 512];      // fp16 k | v
__device__ __align__(128) float  g_pool[NGRAPH * DM];
__device__ __align__(128) float  g_cnt[NGRAPH];
__device__ __align__(128) __half g_xh[N_PAD * DM];         // fp16 activations (row-major)
__device__ __align__(128) __half g_wh[NLAYER * DM * QKVW]; // fp16 W, [l][k][768]
// CSR
__device__ __align__(128) int g_deg[N_NODES];
__device__ __align__(128) int g_rowptr[N_NODES + 1];
__device__ __align__(128) int g_wcnt[N_NODES];
__device__ __align__(128) int g_bsum[SCAN_B];
__device__ __align__(128) int g_boff[SCAN_B];
__device__ __align__(128) int g_csr[N_EDGES];     // (src<<3)|type

__device__ __forceinline__ void red_add_v4(float* addr, float4 v) {
    asm volatile("red.global.add.v4.f32 [%0], {%1,%2,%3,%4};"
                 :: "l"(addr), "f"(v.x), "f"(v.y), "f"(v.z), "f"(v.w) : "memory");
}

// ---------------- MMA helpers ----------------
__device__ __forceinline__ void ldsm4(uint32_t* r, uint32_t addr) {
    asm volatile("ldmatrix.sync.aligned.m8n8.x4.shared.b16 {%0,%1,%2,%3}, [%4];"
                 : "=r"(r[0]), "=r"(r[1]), "=r"(r[2]), "=r"(r[3]) : "r"(addr));
}
__device__ __forceinline__ void ldsm4t(uint32_t* r, uint32_t addr) {
    asm volatile("ldmatrix.sync.aligned.m8n8.x4.trans.shared.b16 {%0,%1,%2,%3}, [%4];"
                 : "=r"(r[0]), "=r"(r[1]), "=r"(r[2]), "=r"(r[3]) : "r"(addr));
}
__device__ __forceinline__ void mma16816(float* c, const uint32_t* a, const uint32_t* b) {
    asm volatile("mma.sync.aligned.m16n8k16.row.col.f32.f16.f16.f32 "
                 "{%0,%1,%2,%3}, {%4,%5,%6,%7}, {%8,%9}, {%0,%1,%2,%3};"
                 : "+f"(c[0]), "+f"(c[1]), "+f"(c[2]), "+f"(c[3])
                 : "r"(a[0]), "r"(a[1]), "r"(a[2]), "r"(a[3]), "r"(b[0]), "r"(b[1]));
}
__device__ __forceinline__ void cp16(uint32_t s, const void* g) {
    asm volatile("cp.async.cg.shared.global [%0], [%1], 16;" :: "r"(s), "l"(g));
}
__device__ __forceinline__ uint32_t smem_u32(const void* p) {
    return (uint32_t)__cvta_generic_to_shared(p);
}

// ---------------- precompute conversions ----------------
__global__ void convert_w_kernel(const float* __restrict__ Wq, const float* __restrict__ Wk,
                                 const float* __restrict__ Wv) {
    int idx = blockIdx.x * blockDim.x + threadIdx.x;
    if (idx >= NLAYER * DM * QKVW) return;
    int l = idx / (DM * QKVW);
    int r = idx - l * (DM * QKVW);
    int k = r / QKVW;
    int n = r - k * QKVW;
    int m = n >> 8;
    const float* W = (m == 0 ? Wq : (m == 1 ? Wk : Wv));
    g_wh[idx] = __float2half(W[l * DM * DM + k * DM + (n & 255)]);
}

// also zeroes deg/pool/cnt (prologue fusion)
__global__ void convert_x_kernel(const float* __restrict__ X) {
    int i4 = blockIdx.x * blockDim.x + threadIdx.x;
    if (i4 < N_NODES) g_deg[i4] = 0;
    if (i4 < NGRAPH * DM) g_pool[i4] = 0.f;
    if (i4 < NGRAPH) g_cnt[i4] = 0.f;
    if (i4 >= N_PAD * 64) return;
    int row = i4 >> 6;
    float4 f = make_float4(0.f, 0.f, 0.f, 0.f);
    if (row < N_NODES) f = ((const float4*)X)[i4];
    __half h[4];
    h[0] = __float2half(f.x); h[1] = __float2half(f.y);
    h[2] = __float2half(f.z); h[3] = __float2half(f.w);
    ((uint2*)g_xh)[i4] = *(uint2*)h;
}

// ---------------- CSR build ----------------
__global__ void hist_kernel(const int* __restrict__ dst) {
    int e = blockIdx.x * blockDim.x + threadIdx.x;
    if (e < N_EDGES) atomicAdd(&g_deg[dst[e]], 1);
}
__global__ void scan1_kernel() {
    __shared__ int sh[1024];
    int t = threadIdx.x, b = blockIdx.x;
    int i = b * 1024 + t;
    int v = (i < N_NODES) ? g_deg[i] : 0;
    sh[t] = v;
    __syncthreads();
    for (int off = 1; off < 1024; off <<= 1) {
        int x = sh[t];
        if (t >= off) x += sh[t - off];
        __syncthreads();
        sh[t] = x;
        __syncthreads();
    }
    if (i < N_NODES) g_rowptr[i] = sh[t] - v;     // block-local exclusive
    if (t == 1023) g_bsum[b] = sh[1023];
}
__global__ void scan2_kernel() {      // 1 thread: 30 elems
    if (threadIdx.x == 0) {
        int run = 0;
        for (int b = 0; b < SCAN_B; b++) { g_boff[b] = run; run += g_bsum[b]; }
        g_rowptr[N_NODES] = run;
    }
}
__global__ void scan3_kernel() {
    int i = blockIdx.x * blockDim.x + threadIdx.x;
    if (i >= N_NODES) return;
    int v = g_rowptr[i] + g_boff[i >> 10];
    g_rowptr[i] = v;
    g_wcnt[i] = v;
}
__global__ void scatter_kernel(const int* __restrict__ src, const int* __restrict__ dst,
                               const int* __restrict__ et) {
    int e = blockIdx.x * blockDim.x + threadIdx.x;
    if (e >= N_EDGES) return;
    int p = atomicAdd(&g_wcnt[dst[e]], 1);
    g_csr[p] = (src[e] << 3) | et[e];
}

// ---------------- tensor-core QKV GEMM (fp16, 128x128 tile, K-chunk 64, 3-stage) -------
__global__ __launch_bounds__(256, 2) void gemm_qkv_mma(
    int layer,
    const float* __restrict__ bq, const float* __restrict__ bk, const float* __restrict__ bv)
{
    extern __shared__ __align__(16) __half smem[];

    const int t = threadIdx.x, lane = t & 31, wid = t >> 5;
    const int warp_m = wid >> 2, warp_n = wid & 3;
    const int bm = blockIdx.x, by = blockIdx.y;       // by in [0,6)
    const __half* Wh = g_wh + (size_t)layer * DM * QKVW;

    float acc[4][4][4];
#pragma unroll
    for (int i = 0; i < 4; i++)
#pragma unroll
        for (int j = 0; j < 4; j++)
#pragma unroll
            for (int c = 0; c < 4; c++) acc[i][j][c] = 0.f;

    // A copy slots: 1024 cp16s over 4 per thread; row = id>>3 (0..127), cg = id&7
    // B copy slots: 1024 cp16s; row = id>>4 (0..63), cg = id&15
#define CP_CHUNK(kc, s) do {                                                          \
        int k0 = (kc) * 64;                                                           \
        __half* st = smem + (s) * STAGE_E;                                            \
        _Pragma("unroll")                                                             \
        for (int i = 0; i < 4; i++) {                                                 \
            int id = t + 256 * i;                                                     \
            int arow = id >> 3, acg = id & 7;                                         \
            cp16(smem_u32(st + arow * ASTRIDE + acg * 8),                             \
                 g_xh + (size_t)(bm * 128 + arow) * 256 + k0 + acg * 8);              \
        }                                                                             \
        _Pragma("unroll")                                                             \
        for (int i = 0; i < 4; i++) {                                                 \
            int id = t + 256 * i;                                                     \
            int brow = id >> 4, bcg = id & 15;                                        \
            cp16(smem_u32(st + OFF_B + brow * BSTRIDE + bcg * 8),                     \
                 Wh + (size_t)(k0 + brow) * QKVW + by * 128 + bcg * 8);               \
        }                                                                             \
        asm volatile("cp.async.commit_group;");                                       \
    } while (0)

    CP_CHUNK(0, 0);
    CP_CHUNK(1, 1);

    const int g = lane >> 3, ri = lane & 7;
    const uint32_t sb0 = smem_u32(smem);

    for (int c = 0; c < 4; c++) {
        if (c < 3) asm volatile("cp.async.wait_group 1;" ::: "memory");
        else       asm volatile("cp.async.wait_group 0;" ::: "memory");
        __syncthreads();                       // also releases stage (c+2)%3 readers
        if (c + 2 < 4) CP_CHUNK(c + 2, (c + 2) % 3);

        const uint32_t base = sb0 + (uint32_t)((c % 3) * STAGE_E * 2);

#pragma unroll
        for (int ks = 0; ks < 64; ks += 16) {
            uint32_t af[4][4];
#pragma unroll
            for (int mt = 0; mt < 4; mt++) {
                uint32_t eoff = (uint32_t)((warp_m * 64 + mt * 16 + (g & 1) * 8 + ri) * ASTRIDE
                                           + ks + (g >> 1) * 8) * 2u;
                ldsm4(af[mt], base + eoff);
            }
            uint32_t bfh[4][2];
#pragma unroll
            for (int ntp = 0; ntp < 2; ntp++) {
                uint32_t boff = (uint32_t)((ks + (g & 1) * 8 + ri) * BSTRIDE
                                           + warp_n * 32 + ntp * 16 + (g >> 1) * 8) * 2u;
                uint32_t r[4];
                ldsm4t(r, base + OFF_B * 2 + boff);
                bfh[ntp * 2][0] = r[0]; bfh[ntp * 2][1] = r[1];
                bfh[ntp * 2 + 1][0] = r[2]; bfh[ntp * 2 + 1][1] = r[3];
            }
#pragma unroll
            for (int mt = 0; mt < 4; mt++)
#pragma unroll
                for (int nt = 0; nt < 4; nt++)
                    mma16816(acc[mt][nt], af[mt], bfh[nt]);
        }
    }

    const int sec = by >> 1;                          // 0=q, 1=k, 2=v
    const float* bias = sec == 0 ? bq : (sec == 1 ? bk : bv);
    const int lcol = (by & 1) * 128;
#pragma unroll
    for (int mt = 0; mt < 4; mt++)
#pragma unroll
        for (int nt = 0; nt < 4; nt++) {
            int r0 = bm * 128 + warp_m * 64 + mt * 16 + (lane >> 2);
            int ocol = warp_n * 32 + nt * 8 + (lane & 3) * 2;
            float b0 = bias[lcol + ocol], b1 = bias[lcol + ocol + 1];
            if (sec == 0) {
                if (r0 < N_NODES)
                    *(float2*)(g_q + (size_t)r0 * DM + lcol + ocol) =
                        make_float2(acc[mt][nt][0] + b0, acc[mt][nt][1] + b1);
                if (r0 + 8 < N_NODES)
                    *(float2*)(g_q + (size_t)(r0 + 8) * DM + lcol + ocol) =
                        make_float2(acc[mt][nt][2] + b0, acc[mt][nt][3] + b1);
            } else {
                size_t cbase = (size_t)(sec - 1) * 256 + lcol + ocol;
                if (r0 < N_NODES)
                    *(__half2*)(g_kv + (size_t)r0 * 512 + cbase) =
                        __floats2half2_rn(acc[mt][nt][0] + b0, acc[mt][nt][1] + b1);
                if (r0 + 8 < N_NODES)
                    *(__half2*)(g_kv + (size_t)(r0 + 8) * 512 + cbase) =
                        __floats2half2_rn(acc[mt][nt][2] + b0, acc[mt][nt][3] + b1);
            }
        }
#undef CP_CHUNK
}

// ---------------- fused attention: warp/dst, online softmax + ELU; 2x unrolled ----------
__global__ __launch_bounds__(256) void attn_kernel(const float* __restrict__ Ee,
                                                   const int* __restrict__ batch, int final_l)
{
    int d = (blockIdx.x * blockDim.x + threadIdx.x) >> 5;
    if (d >= N_NODES) return;
    int lane = threadIdx.x & 31;

    const float4* qp = (const float4*)(g_q + (size_t)d * DM) + lane * 2;
    float4 q0 = qp[0], q1 = qp[1];

    int e0i = g_rowptr[d], e1i = g_rowptr[d + 1];
    float m = -1e30f, den = 0.f;
    float acc[8];
#pragma unroll
    for (int j = 0; j < 8; j++) acc[j] = 0.f;

    int e = e0i;
    for (; e + 2 <= e1i; e += 2) {
        int p0 = g_csr[e], p1 = g_csr[e + 1];
        int s0 = p0 >> 3, ty0 = p0 & 7;
        int s1 = p1 >> 3, ty1 = p1 & 7;
        uint4 k0r = *(const uint4*)(g_kv + (size_t)s0 * 512 + lane * 8);
        uint4 v0r = *(const uint4*)(g_kv + (size_t)s0 * 512 + 256 + lane * 8);
        uint4 k1r = *(const uint4*)(g_kv + (size_t)s1 * 512 + lane * 8);
        uint4 v1r = *(const uint4*)(g_kv + (size_t)s1 * 512 + 256 + lane * 8);
        const float4* e0p = (const float4*)(Ee + ty0 * 256) + lane * 2;
        const float4* e1p = (const float4*)(Ee + ty1 * 256) + lane * 2;
        float4 ea0 = e0p[0], ea1 = e0p[1];
        float4 eb0 = e1p[0], eb1 = e1p[1];

        float ke0[8], ve0[8], ke1[8], ve1[8];
        {
            float2 kf[4], vf[4];
            kf[0] = __half22float2(*(__half2*)&k0r.x); kf[1] = __half22float2(*(__half2*)&k0r.y);
            kf[2] = __half22float2(*(__half2*)&k0r.z); kf[3] = __half22float2(*(__half2*)&k0r.w);
            vf[0] = __half22float2(*(__half2*)&v0r.x); vf[1] = __half22float2(*(__half2*)&v0r.y);
            vf[2] = __half22float2(*(__half2*)&v0r.z); vf[3] = __half22float2(*(__half2*)&v0r.w);
            ke0[0]=kf[0].x+ea0.x; ke0[1]=kf[0].y+ea0.y; ke0[2]=kf[1].x+ea0.z; ke0[3]=kf[1].y+ea0.w;
            ke0[4]=kf[2].x+ea1.x; ke0[5]=kf[2].y+ea1.y; ke0[6]=kf[3].x+ea1.z; ke0[7]=kf[3].y+ea1.w;
            ve0[0]=vf[0].x+ea0.x; ve0[1]=vf[0].y+ea0.y; ve0[2]=vf[1].x+ea0.z; ve0[3]=vf[1].y+ea0.w;
            ve0[4]=vf[2].x+ea1.x; ve0[5]=vf[2].y+ea1.y; ve0[6]=vf[3].x+ea1.z; ve0[7]=vf[3].y+ea1.w;
        }
        {
            float2 kf[4], vf[4];
            kf[0] = __half22float2(*(__half2*)&k1r.x); kf[1] = __half22float2(*(__half2*)&k1r.y);
            kf[2] = __half22float2(*(__half2*)&k1r.z); kf[3] = __half22float2(*(__half2*)&k1r.w);
            vf[0] = __half22float2(*(__half2*)&v1r.x); vf[1] = __half22float2(*(__half2*)&v1r.y);
            vf[2] = __half22float2(*(__half2*)&v1r.z); vf[3] = __half22float2(*(__half2*)&v1r.w);
            ke1[0]=kf[0].x+eb0.x; ke1[1]=kf[0].y+eb0.y; ke1[2]=kf[1].x+eb0.z; ke1[3]=kf[1].y+eb0.w;
            ke1[4]=kf[2].x+eb1.x; ke1[5]=kf[2].y+eb1.y; ke1[6]=kf[3].x+eb1.z; ke1[7]=kf[3].y+eb1.w;
            ve1[0]=vf[0].x+eb0.x; ve1[1]=vf[0].y+eb0.y; ve1[2]=vf[1].x+eb0.z; ve1[3]=vf[1].y+eb0.w;
            ve1[4]=vf[2].x+eb1.x; ve1[5]=vf[2].y+eb1.y; ve1[6]=vf[3].x+eb1.z; ve1[7]=vf[3].y+eb1.w;
        }

        float pa = q0.x*ke0[0]+q0.y*ke0[1]+q0.z*ke0[2]+q0.w*ke0[3]
                 + q1.x*ke0[4]+q1.y*ke0[5]+q1.z*ke0[6]+q1.w*ke0[7];
        float pb = q0.x*ke1[0]+q0.y*ke1[1]+q0.z*ke1[2]+q0.w*ke1[3]
                 + q1.x*ke1[4]+q1.y*ke1[5]+q1.z*ke1[6]+q1.w*ke1[7];
        pa += __shfl_xor_sync(0xffffffffu, pa, 1, 8);
        pb += __shfl_xor_sync(0xffffffffu, pb, 1, 8);
        pa += __shfl_xor_sync(0xffffffffu, pa, 2, 8);
        pb += __shfl_xor_sync(0xffffffffu, pb, 2, 8);
        pa += __shfl_xor_sync(0xffffffffu, pa, 4, 8);
        pb += __shfl_xor_sync(0xffffffffu, pb, 4, 8);
        float sc0 = pa * 0.125f, sc1 = pb * 0.125f;

        float mn = fmaxf(m, sc0);
        float scale = __expf(m - mn);
        float w = __expf(sc0 - mn);
        den = den * scale + w;
#pragma unroll
        for (int j = 0; j < 8; j++) acc[j] = acc[j] * scale + w * ve0[j];
        m = mn;

        mn = fmaxf(m, sc1);
        scale = __expf(m - mn);
        w = __expf(sc1 - mn);
        den = den * scale + w;
#pragma unroll
        for (int j = 0; j < 8; j++) acc[j] = acc[j] * scale + w * ve1[j];
        m = mn;
    }
    if (e < e1i) {
        int p0 = g_csr[e];
        int s0 = p0 >> 3, ty0 = p0 & 7;
        uint4 k0r = *(const uint4*)(g_kv + (size_t)s0 * 512 + lane * 8);
        uint4 v0r = *(const uint4*)(g_kv + (size_t)s0 * 512 + 256 + lane * 8);
        const float4* e0p = (const float4*)(Ee + ty0 * 256) + lane * 2;
        float4 ea0 = e0p[0], ea1 = e0p[1];
        float2 kf[4], vf[4];
        kf[0] = __half22float2(*(__half2*)&k0r.x); kf[1] = __half22float2(*(__half2*)&k0r.y);
        kf[2] = __half22float2(*(__half2*)&k0r.z); kf[3] = __half22float2(*(__half2*)&k0r.w);
        vf[0] = __half22float2(*(__half2*)&v0r.x); vf[1] = __half22float2(*(__half2*)&v0r.y);
        vf[2] = __half22float2(*(__half2*)&v0r.z); vf[3] = __half22float2(*(__half2*)&v0r.w);
        float ke0[8], ve0[8];
        ke0[0]=kf[0].x+ea0.x; ke0[1]=kf[0].y+ea0.y; ke0[2]=kf[1].x+ea0.z; ke0[3]=kf[1].y+ea0.w;
        ke0[4]=kf[2].x+ea1.x; ke0[5]=kf[2].y+ea1.y; ke0[6]=kf[3].x+ea1.z; ke0[7]=kf[3].y+ea1.w;
        ve0[0]=vf[0].x+ea0.x; ve0[1]=vf[0].y+ea0.y; ve0[2]=vf[1].x+ea0.z; ve0[3]=vf[1].y+ea0.w;
        ve0[4]=vf[2].x+ea1.x; ve0[5]=vf[2].y+ea1.y; ve0[6]=vf[3].x+ea1.z; ve0[7]=vf[3].y+ea1.w;
        float pa = q0.x*ke0[0]+q0.y*ke0[1]+q0.z*ke0[2]+q0.w*ke0[3]
                 + q1.x*ke0[4]+q1.y*ke0[5]+q1.z*ke0[6]+q1.w*ke0[7];
        pa += __shfl_xor_sync(0xffffffffu, pa, 1, 8);
        pa += __shfl_xor_sync(0xffffffffu, pa, 2, 8);
        pa += __shfl_xor_sync(0xffffffffu, pa, 4, 8);
        float sc0 = pa * 0.125f;
        float mn = fmaxf(m, sc0);
        float scale = __expf(m - mn);
        float w = __expf(sc0 - mn);
        den = den * scale + w;
#pragma unroll
        for (int j = 0; j < 8; j++) acc[j] = acc[j] * scale + w * ve0[j];
        m = mn;
    }

    float inv = den > 0.f ? 1.f / den : 0.f;
    float o[8];
#pragma unroll
    for (int j = 0; j < 8; j++) {
        float v = acc[j] * inv;
        o[j] = v > 0.f ? v : expm1f(v);
    }
    if (final_l) {
        int b = batch[d];
        float* p = g_pool + (size_t)b * DM + lane * 8;
        red_add_v4(p,     make_float4(o[0], o[1], o[2], o[3]));
        red_add_v4(p + 4, make_float4(o[4], o[5], o[6], o[7]));
        if (lane == 0) atomicAdd(&g_cnt[b], 1.0f);
    } else {
        __half h[8];
#pragma unroll
        for (int j = 0; j < 8; j++) h[j] = __float2half(o[j]);
        *(uint4*)(g_xh + (size_t)d * DM + lane * 8) = *(uint4*)h;
    }
}

// ---------------- GRU + FC ----------------
__global__ void gru_fc(const float* __restrict__ W_ih, const float* __restrict__ b_ih,
                       const float* __restrict__ b_hh,
                       const float* __restrict__ W_fc, const float* __restrict__ b_fc,
                       float* __restrict__ out)
{
    __shared__ float gsh[256];
    __shared__ float gish[192];
    __shared__ float hsh[64];
    int b = blockIdx.x;
    int t = threadIdx.x;
    float inv = 1.0f / fmaxf(g_cnt[b], 1.0f);
    gsh[t] = g_pool[b * DM + t] * inv;
    __syncthreads();
    if (t < 192) {
        float s = b_ih[t];
        const float* w = W_ih + t * 256;
#pragma unroll 8
        for (int k = 0; k < 256; k++) s += gsh[k] * w[k];
        gish[t] = s;
    }
    __syncthreads();
    if (t < 64) {
        float r = 1.f / (1.f + expf(-(gish[t] + b_hh[t])));
        float z = 1.f / (1.f + expf(-(gish[64 + t] + b_hh[64 + t])));
        float n = tanhf(gish[128 + t] + r * b_hh[128 + t]);
        hsh[t] = (1.f - z) * n;
    }
    __syncthreads();
    if (t < 2) {
        float s = b_fc[t];
        const float* w = W_fc + t * 64;
#pragma unroll
        for (int k = 0; k < 64; k++) s += hsh[k] * w[k];
        out[b * 2 + t] = s;
    }
}

// ---------------- launch ----------------
extern "C" void kernel_launch(void* const* d_in, const int* in_sizes, int n_in,
                              void* d_out, int out_size)
{
    const float* x     = (const float*)d_in[0];
    const int*   eidx  = (const int*)d_in[1];
    const int*   batch = (const int*)d_in[2];
    const int*   etid  = (const int*)d_in[3];
    const float* Wq    = (const float*)d_in[4];
    const float* bq    = (const float*)d_in[5];
    const float* Wk    = (const float*)d_in[6];
    const float* bk    = (const float*)d_in[7];
    const float* Wv    = (const float*)d_in[8];
    const float* bv    = (const float*)d_in[9];
    const float* Ee    = (const float*)d_in[10];
    const float* W_ih  = (const float*)d_in[11];
    const float* b_ih  = (const float*)d_in[12];
    const float* b_hh  = (const float*)d_in[14];
    const float* W_fc  = (const float*)d_in[15];
    const float* b_fc  = (const float*)d_in[16];

    const int* src = eidx;
    const int* dst = eidx + N_EDGES;

    static int smem_set = 0;
    const int gemm_smem = 3 * STAGE_E * (int)sizeof(__half);   // 107520 B
    if (!smem_set) {
        cudaFuncSetAttribute(gemm_qkv_mma, cudaFuncAttributeMaxDynamicSharedMemorySize, gemm_smem);
        smem_set = 1;
    }

    dim3 ggrid(N_PAD / 128, 6);

    // launch order arranged so gemm layer-0 is launch index 5 (ncu -s 5 -c 1)
    convert_w_kernel<<<(NLAYER * DM * QKVW + 255) / 256, 256>>>(Wq, Wk, Wv);   // 0
    convert_x_kernel<<<(N_PAD * 64 + 255) / 256, 256>>>(x);                    // 1 (zeroes deg)
    hist_kernel<<<(N_EDGES + 255) / 256, 256>>>(dst);                          // 2
    scan1_kernel<<<SCAN_B, 1024>>>();                                          // 3
    scan2_kernel<<<1, 32>>>();                                                 // 4
    gemm_qkv_mma<<<ggrid, 256, gemm_smem>>>(0, bq, bk, bv);                    // 5  <- profiled
    scan3_kernel<<<(N_NODES + 255) / 256, 256>>>();                            // 6
    scatter_kernel<<<(N_EDGES + 255) / 256, 256>>>(src, dst, etid);            // 7

    for (int l = 0; l < NLAYER; l++) {
        if (l > 0)
            gemm_qkv_mma<<<ggrid, 256, gemm_smem>>>(l, bq + l * DM, bk + l * DM, bv + l * DM);
        attn_kernel<<<(N_NODES * 32 + 255) / 256, 256>>>(Ee + l * 8 * DM, batch,
                                                         l == NLAYER - 1 ? 1 : 0);
    }
    gru_fc<<<NGRAPH, 256>>>(W_ih, b_ih, b_hh, W_fc, b_fc, (float*)d_out);
}

// round 16
// speedup vs baseline: 1.0304x; 1.0304x over previous
#include <cuda_runtime.h>
#include <cuda_fp16.h>
#include <cstdint>

#define N_NODES 30000
#define N_PAD   30080           // 235 * 128
#define N_EDGES 240000
#define DM 256
#define QKVW 768
#define NGRAPH 64
#define NLAYER 3
#define SCAN_B  30              // ceil(30000/1024)

// GEMM smem layout (fp16 elems per stage): Ah 128x40, Bh 32x136
#define ASTRIDE 40
#define BSTRIDE 136
#define OFF_BH  5120
#define STAGE_E 9472            // elems per stage (18944 B); 4 stages = 75776 B

// ---------------- scratch ----------------
__device__ __align__(128) __half g_qh[N_NODES * DM];       // fp16 q (512B rows)
__device__ __align__(128) __half g_kv[N_NODES * 512];      // fp16 k | v
__device__ __align__(128) float  g_pool[NGRAPH * DM];
__device__ __align__(128) float  g_cnt[NGRAPH];
__device__ __align__(128) __half g_xh[N_PAD * DM];         // fp16 activations (row-major)
__device__ __align__(128) __half g_wh[NLAYER * DM * QKVW]; // fp16 W, [l][k][768]
// CSR
__device__ __align__(128) int g_deg[N_NODES];
__device__ __align__(128) int g_rowptr[N_NODES + 1];
__device__ __align__(128) int g_wcnt[N_NODES];
__device__ __align__(128) int g_bsum[SCAN_B];
__device__ __align__(128) int g_boff[SCAN_B];
__device__ __align__(128) int g_csr[N_EDGES];     // (src<<3)|type

__device__ __forceinline__ void red_add_v4(float* addr, float4 v) {
    asm volatile("red.global.add.v4.f32 [%0], {%1,%2,%3,%4};"
                 :: "l"(addr), "f"(v.x), "f"(v.y), "f"(v.z), "f"(v.w) : "memory");
}

// ---------------- MMA helpers ----------------
__device__ __forceinline__ void ldsm4(uint32_t* r, uint32_t addr) {
    asm volatile("ldmatrix.sync.aligned.m8n8.x4.shared.b16 {%0,%1,%2,%3}, [%4];"
                 : "=r"(r[0]), "=r"(r[1]), "=r"(r[2]), "=r"(r[3]) : "r"(addr));
}
__device__ __forceinline__ void ldsm4t(uint32_t* r, uint32_t addr) {
    asm volatile("ldmatrix.sync.aligned.m8n8.x4.trans.shared.b16 {%0,%1,%2,%3}, [%4];"
                 : "=r"(r[0]), "=r"(r[1]), "=r"(r[2]), "=r"(r[3]) : "r"(addr));
}
__device__ __forceinline__ void mma16816(float* c, const uint32_t* a, const uint32_t* b) {
    asm volatile("mma.sync.aligned.m16n8k16.row.col.f32.f16.f16.f32 "
                 "{%0,%1,%2,%3}, {%4,%5,%6,%7}, {%8,%9}, {%0,%1,%2,%3};"
                 : "+f"(c[0]), "+f"(c[1]), "+f"(c[2]), "+f"(c[3])
                 : "r"(a[0]), "r"(a[1]), "r"(a[2]), "r"(a[3]), "r"(b[0]), "r"(b[1]));
}
__device__ __forceinline__ void cp16(uint32_t s, const void* g) {
    asm volatile("cp.async.cg.shared.global [%0], [%1], 16;" :: "r"(s), "l"(g));
}
__device__ __forceinline__ uint32_t smem_u32(const void* p) {
    return (uint32_t)__cvta_generic_to_shared(p);
}

// ---------------- precompute conversions ----------------
__global__ void convert_w_kernel(const float* __restrict__ Wq, const float* __restrict__ Wk,
                                 const float* __restrict__ Wv) {
    int idx = blockIdx.x * blockDim.x + threadIdx.x;
    if (idx >= NLAYER * DM * QKVW) return;
    int l = idx / (DM * QKVW);
    int r = idx - l * (DM * QKVW);
    int k = r / QKVW;
    int n = r - k * QKVW;
    int m = n >> 8;
    const float* W = (m == 0 ? Wq : (m == 1 ? Wk : Wv));
    g_wh[idx] = __float2half(W[l * DM * DM + k * DM + (n & 255)]);
}

// also zeroes deg/pool/cnt (prologue fusion)
__global__ void convert_x_kernel(const float* __restrict__ X) {
    int i4 = blockIdx.x * blockDim.x + threadIdx.x;
    if (i4 < N_NODES) g_deg[i4] = 0;
    if (i4 < NGRAPH * DM) g_pool[i4] = 0.f;
    if (i4 < NGRAPH) g_cnt[i4] = 0.f;
    if (i4 >= N_PAD * 64) return;
    int row = i4 >> 6;
    float4 f = make_float4(0.f, 0.f, 0.f, 0.f);
    if (row < N_NODES) f = ((const float4*)X)[i4];
    __half h[4];
    h[0] = __float2half(f.x); h[1] = __float2half(f.y);
    h[2] = __float2half(f.z); h[3] = __float2half(f.w);
    ((uint2*)g_xh)[i4] = *(uint2*)h;
}

// ---------------- CSR build ----------------
__global__ void hist_kernel(const int* __restrict__ dst) {
    int e = blockIdx.x * blockDim.x + threadIdx.x;
    if (e < N_EDGES) atomicAdd(&g_deg[dst[e]], 1);
}
__global__ void scan1_kernel() {
    __shared__ int sh[1024];
    int t = threadIdx.x, b = blockIdx.x;
    int i = b * 1024 + t;
    int v = (i < N_NODES) ? g_deg[i] : 0;
    sh[t] = v;
    __syncthreads();
    for (int off = 1; off < 1024; off <<= 1) {
        int x = sh[t];
        if (t >= off) x += sh[t - off];
        __syncthreads();
        sh[t] = x;
        __syncthreads();
    }
    if (i < N_NODES) g_rowptr[i] = sh[t] - v;     // block-local exclusive
    if (t == 1023) g_bsum[b] = sh[1023];
}
__global__ void scan2_kernel() {      // 1 thread: 30 elems
    if (threadIdx.x == 0) {
        int run = 0;
        for (int b = 0; b < SCAN_B; b++) { g_boff[b] = run; run += g_bsum[b]; }
        g_rowptr[N_NODES] = run;
    }
}
__global__ void scan3_kernel() {
    int i = blockIdx.x * blockDim.x + threadIdx.x;
    if (i >= N_NODES) return;
    int v = g_rowptr[i] + g_boff[i >> 10];
    g_rowptr[i] = v;
    g_wcnt[i] = v;
}
__global__ void scatter_kernel(const int* __restrict__ src, const int* __restrict__ dst,
                               const int* __restrict__ et) {
    int e = blockIdx.x * blockDim.x + threadIdx.x;
    if (e >= N_EDGES) return;
    int p = atomicAdd(&g_wcnt[dst[e]], 1);
    g_csr[p] = (src[e] << 3) | et[e];
}

// ---------------- tensor-core QKV GEMM (fp16, 128x128 tile, 4-stage) ----------------
__global__ __launch_bounds__(256, 2) void gemm_qkv_mma(
    int layer,
    const float* __restrict__ bq, const float* __restrict__ bk, const float* __restrict__ bv)
{
    extern __shared__ __align__(16) __half smem[];

    const int t = threadIdx.x, lane = t & 31, wid = t >> 5;
    const int warp_m = wid >> 2, warp_n = wid & 3;
    const int bm = blockIdx.x, by = blockIdx.y;       // by in [0,6)
    const __half* Wh = g_wh + (size_t)layer * DM * QKVW;

    float acc[4][4][4];
#pragma unroll
    for (int i = 0; i < 4; i++)
#pragma unroll
        for (int j = 0; j < 4; j++)
#pragma unroll
            for (int c = 0; c < 4; c++) acc[i][j][c] = 0.f;

    const int a_row0 = t >> 2,         a_cg0 = t & 3;
    const int a_row1 = (t + 256) >> 2, a_cg1 = t & 3;
    const int b_row0 = t >> 4,         b_cg0 = t & 15;
    const int b_row1 = (t + 256) >> 4, b_cg1 = t & 15;

#define CP_CHUNK(kc, s) do {                                                          \
        int k0 = (kc) * 32;                                                           \
        __half* st = smem + (s) * STAGE_E;                                            \
        cp16(smem_u32(st + a_row0 * ASTRIDE + a_cg0 * 8),                             \
             g_xh + (size_t)(bm * 128 + a_row0) * 256 + k0 + a_cg0 * 8);              \
        cp16(smem_u32(st + a_row1 * ASTRIDE + a_cg1 * 8),                             \
             g_xh + (size_t)(bm * 128 + a_row1) * 256 + k0 + a_cg1 * 8);              \
        cp16(smem_u32(st + OFF_BH + b_row0 * BSTRIDE + b_cg0 * 8),                    \
             Wh + (size_t)(k0 + b_row0) * QKVW + by * 128 + b_cg0 * 8);               \
        cp16(smem_u32(st + OFF_BH + b_row1 * BSTRIDE + b_cg1 * 8),                    \
             Wh + (size_t)(k0 + b_row1) * QKVW + by * 128 + b_cg1 * 8);               \
        asm volatile("cp.async.commit_group;");                                       \
    } while (0)

    CP_CHUNK(0, 0);
    CP_CHUNK(1, 1);

    const int g = lane >> 3, ri = lane & 7;
    const uint32_t sb0 = smem_u32(smem);

    for (int kc = 0; kc < 8; kc++) {
        if (kc < 6) {
            CP_CHUNK(kc + 2, (kc + 2) & 3);
            asm volatile("cp.async.wait_group 2;" ::: "memory");
        } else if (kc == 6) {
            asm volatile("cp.async.wait_group 1;" ::: "memory");
        } else {
            asm volatile("cp.async.wait_group 0;" ::: "memory");
        }
        __syncthreads();

        const uint32_t base = sb0 + (uint32_t)((kc & 3) * STAGE_E * 2);

#pragma unroll
        for (int ks = 0; ks < 32; ks += 16) {
            uint32_t af[4][4];
#pragma unroll
            for (int mt = 0; mt < 4; mt++) {
                uint32_t eoff = (uint32_t)((warp_m * 64 + mt * 16 + (g & 1) * 8 + ri) * ASTRIDE
                                           + ks + (g >> 1) * 8) * 2u;
                ldsm4(af[mt], base + eoff);
            }
            uint32_t bfh[4][2];
#pragma unroll
            for (int ntp = 0; ntp < 2; ntp++) {
                uint32_t boff = (uint32_t)((ks + (g & 1) * 8 + ri) * BSTRIDE
                                           + warp_n * 32 + ntp * 16 + (g >> 1) * 8) * 2u;
                uint32_t r[4];
                ldsm4t(r, base + OFF_BH * 2 + boff);
                bfh[ntp * 2][0] = r[0]; bfh[ntp * 2][1] = r[1];
                bfh[ntp * 2 + 1][0] = r[2]; bfh[ntp * 2 + 1][1] = r[3];
            }
#pragma unroll
            for (int mt = 0; mt < 4; mt++)
#pragma unroll
                for (int nt = 0; nt < 4; nt++)
                    mma16816(acc[mt][nt], af[mt], bfh[nt]);
        }
    }

    const int sec = by >> 1;                          // 0=q, 1=k, 2=v
    const float* bias = sec == 0 ? bq : (sec == 1 ? bk : bv);
    const int lcol = (by & 1) * 128;
#pragma unroll
    for (int mt = 0; mt < 4; mt++)
#pragma unroll
        for (int nt = 0; nt < 4; nt++) {
            int r0 = bm * 128 + warp_m * 64 + mt * 16 + (lane >> 2);
            int ocol = warp_n * 32 + nt * 8 + (lane & 3) * 2;
            float b0 = bias[lcol + ocol], b1 = bias[lcol + ocol + 1];
            __half* dest0;
            __half* dest1;
            if (sec == 0) {
                dest0 = g_qh + (size_t)r0 * DM + lcol + ocol;
                dest1 = g_qh + (size_t)(r0 + 8) * DM + lcol + ocol;
            } else {
                size_t cbase = (size_t)(sec - 1) * 256 + lcol + ocol;
                dest0 = g_kv + (size_t)r0 * 512 + cbase;
                dest1 = g_kv + (size_t)(r0 + 8) * 512 + cbase;
            }
            if (r0 < N_NODES)
                *(__half2*)dest0 = __floats2half2_rn(acc[mt][nt][0] + b0, acc[mt][nt][1] + b1);
            if (r0 + 8 < N_NODES)
                *(__half2*)dest1 = __floats2half2_rn(acc[mt][nt][2] + b0, acc[mt][nt][3] + b1);
        }
#undef CP_CHUNK
}

// ---------------- fused attention: warp/dst, online softmax + ELU; 2x unrolled ----------
__global__ __launch_bounds__(256) void attn_kernel(const float* __restrict__ Ee,
                                                   const int* __restrict__ batch, int final_l)
{
    int d = (blockIdx.x * blockDim.x + threadIdx.x) >> 5;
    if (d >= N_NODES) return;
    int lane = threadIdx.x & 31;

    float4 q0, q1;
    {
        uint4 qr = *(const uint4*)(g_qh + (size_t)d * DM + lane * 8);
        float2 f;
        f = __half22float2(*(__half2*)&qr.x);     q0.x = f.x; q0.y = f.y;
        f = __half22float2(((__half2*)&qr.x)[1]); q0.z = f.x; q0.w = f.y;
        f = __half22float2(*(__half2*)&qr.z);     q1.x = f.x; q1.y = f.y;
        f = __half22float2(((__half2*)&qr.z)[1]); q1.z = f.x; q1.w = f.y;
    }

    int e0i = g_rowptr[d], e1i = g_rowptr[d + 1];
    float m = -1e30f, den = 0.f;
    float acc[8];
#pragma unroll
    for (int j = 0; j < 8; j++) acc[j] = 0.f;

    int e = e0i;
    for (; e + 2 <= e1i; e += 2) {
        int p0 = g_csr[e], p1 = g_csr[e + 1];
        int s0 = p0 >> 3, ty0 = p0 & 7;
        int s1 = p1 >> 3, ty1 = p1 & 7;
        uint4 k0r = *(const uint4*)(g_kv + (size_t)s0 * 512 + lane * 8);
        uint4 v0r = *(const uint4*)(g_kv + (size_t)s0 * 512 + 256 + lane * 8);
        uint4 k1r = *(const uint4*)(g_kv + (size_t)s1 * 512 + lane * 8);
        uint4 v1r = *(const uint4*)(g_kv + (size_t)s1 * 512 + 256 + lane * 8);
        const float4* e0p = (const float4*)(Ee + ty0 * 256) + lane * 2;
        const float4* e1p = (const float4*)(Ee + ty1 * 256) + lane * 2;
        float4 ea0 = e0p[0], ea1 = e0p[1];
        float4 eb0 = e1p[0], eb1 = e1p[1];

        float ke0[8], ve0[8], ke1[8], ve1[8];
        {
            float2 kf[4], vf[4];
            kf[0] = __half22float2(*(__half2*)&k0r.x); kf[1] = __half22float2(*(__half2*)&k0r.y);
            kf[2] = __half22float2(*(__half2*)&k0r.z); kf[3] = __half22float2(*(__half2*)&k0r.w);
            vf[0] = __half22float2(*(__half2*)&v0r.x); vf[1] = __half22float2(*(__half2*)&v0r.y);
            vf[2] = __half22float2(*(__half2*)&v0r.z); vf[3] = __half22float2(*(__half2*)&v0r.w);
            ke0[0]=kf[0].x+ea0.x; ke0[1]=kf[0].y+ea0.y; ke0[2]=kf[1].x+ea0.z; ke0[3]=kf[1].y+ea0.w;
            ke0[4]=kf[2].x+ea1.x; ke0[5]=kf[2].y+ea1.y; ke0[6]=kf[3].x+ea1.z; ke0[7]=kf[3].y+ea1.w;
            ve0[0]=vf[0].x+ea0.x; ve0[1]=vf[0].y+ea0.y; ve0[2]=vf[1].x+ea0.z; ve0[3]=vf[1].y+ea0.w;
            ve0[4]=vf[2].x+ea1.x; ve0[5]=vf[2].y+ea1.y; ve0[6]=vf[3].x+ea1.z; ve0[7]=vf[3].y+ea1.w;
        }
        {
            float2 kf[4], vf[4];
            kf[0] = __half22float2(*(__half2*)&k1r.x); kf[1] = __half22float2(*(__half2*)&k1r.y);
            kf[2] = __half22float2(*(__half2*)&k1r.z); kf[3] = __half22float2(*(__half2*)&k1r.w);
            vf[0] = __half22float2(*(__half2*)&v1r.x); vf[1] = __half22float2(*(__half2*)&v1r.y);
            vf[2] = __half22float2(*(__half2*)&v1r.z); vf[3] = __half22float2(*(__half2*)&v1r.w);
            ke1[0]=kf[0].x+eb0.x; ke1[1]=kf[0].y+eb0.y; ke1[2]=kf[1].x+eb0.z; ke1[3]=kf[1].y+eb0.w;
            ke1[4]=kf[2].x+eb1.x; ke1[5]=kf[2].y+eb1.y; ke1[6]=kf[3].x+eb1.z; ke1[7]=kf[3].y+eb1.w;
            ve1[0]=vf[0].x+eb0.x; ve1[1]=vf[0].y+eb0.y; ve1[2]=vf[1].x+eb0.z; ve1[3]=vf[1].y+eb0.w;
            ve1[4]=vf[2].x+eb1.x; ve1[5]=vf[2].y+eb1.y; ve1[6]=vf[3].x+eb1.z; ve1[7]=vf[3].y+eb1.w;
        }

        float pa = q0.x*ke0[0]+q0.y*ke0[1]+q0.z*ke0[2]+q0.w*ke0[3]
                 + q1.x*ke0[4]+q1.y*ke0[5]+q1.z*ke0[6]+q1.w*ke0[7];
        float pb = q0.x*ke1[0]+q0.y*ke1[1]+q0.z*ke1[2]+q0.w*ke1[3]
                 + q1.x*ke1[4]+q1.y*ke1[5]+q1.z*ke1[6]+q1.w*ke1[7];
        pa += __shfl_xor_sync(0xffffffffu, pa, 1, 8);
        pb += __shfl_xor_sync(0xffffffffu, pb, 1, 8);
        pa += __shfl_xor_sync(0xffffffffu, pa, 2, 8);
        pb += __shfl_xor_sync(0xffffffffu, pb, 2, 8);
        pa += __shfl_xor_sync(0xffffffffu, pa, 4, 8);
        pb += __shfl_xor_sync(0xffffffffu, pb, 4, 8);
        float sc0 = pa * 0.125f, sc1 = pb * 0.125f;

        float mn = fmaxf(m, sc0);
        float scale = __expf(m - mn);
        float w = __expf(sc0 - mn);
        den = den * scale + w;
#pragma unroll
        for (int j = 0; j < 8; j++) acc[j] = acc[j] * scale + w * ve0[j];
        m = mn;

        mn = fmaxf(m, sc1);
        scale = __expf(m - mn);
        w = __expf(sc1 - mn);
        den = den * scale + w;
#pragma unroll
        for (int j = 0; j < 8; j++) acc[j] = acc[j] * scale + w * ve1[j];
        m = mn;
    }
    if (e < e1i) {
        int p0 = g_csr[e];
        int s0 = p0 >> 3, ty0 = p0 & 7;
        uint4 k0r = *(const uint4*)(g_kv + (size_t)s0 * 512 + lane * 8);
        uint4 v0r = *(const uint4*)(g_kv + (size_t)s0 * 512 + 256 + lane * 8);
        const float4* e0p = (const float4*)(Ee + ty0 * 256) + lane * 2;
        float4 ea0 = e0p[0], ea1 = e0p[1];
        float2 kf[4], vf[4];
        kf[0] = __half22float2(*(__half2*)&k0r.x); kf[1] = __half22float2(*(__half2*)&k0r.y);
        kf[2] = __half22float2(*(__half2*)&k0r.z); kf[3] = __half22float2(*(__half2*)&k0r.w);
        vf[0] = __half22float2(*(__half2*)&v0r.x); vf[1] = __half22float2(*(__half2*)&v0r.y);
        vf[2] = __half22float2(*(__half2*)&v0r.z); vf[3] = __half22float2(*(__half2*)&v0r.w);
        float ke0[8], ve0[8];
        ke0[0]=kf[0].x+ea0.x; ke0[1]=kf[0].y+ea0.y; ke0[2]=kf[1].x+ea0.z; ke0[3]=kf[1].y+ea0.w;
        ke0[4]=kf[2].x+ea1.x; ke0[5]=kf[2].y+ea1.y; ke0[6]=kf[3].x+ea1.z; ke0[7]=kf[3].y+ea1.w;
        ve0[0]=vf[0].x+ea0.x; ve0[1]=vf[0].y+ea0.y; ve0[2]=vf[1].x+ea0.z; ve0[3]=vf[1].y+ea0.w;
        ve0[4]=vf[2].x+ea1.x; ve0[5]=vf[2].y+ea1.y; ve0[6]=vf[3].x+ea1.z; ve0[7]=vf[3].y+ea1.w;
        float pa = q0.x*ke0[0]+q0.y*ke0[1]+q0.z*ke0[2]+q0.w*ke0[3]
                 + q1.x*ke0[4]+q1.y*ke0[5]+q1.z*ke0[6]+q1.w*ke0[7];
        pa += __shfl_xor_sync(0xffffffffu, pa, 1, 8);
        pa += __shfl_xor_sync(0xffffffffu, pa, 2, 8);
        pa += __shfl_xor_sync(0xffffffffu, pa, 4, 8);
        float sc0 = pa * 0.125f;
        float mn = fmaxf(m, sc0);
        float scale = __expf(m - mn);
        float w = __expf(sc0 - mn);
        den = den * scale + w;
#pragma unroll
        for (int j = 0; j < 8; j++) acc[j] = acc[j] * scale + w * ve0[j];
        m = mn;
    }

    float inv = den > 0.f ? 1.f / den : 0.f;
    float o[8];
#pragma unroll
    for (int j = 0; j < 8; j++) {
        float v = acc[j] * inv;
        o[j] = v > 0.f ? v : expm1f(v);
    }
    if (final_l) {
        int b = batch[d];
        float* p = g_pool + (size_t)b * DM + lane * 8;
        red_add_v4(p,     make_float4(o[0], o[1], o[2], o[3]));
        red_add_v4(p + 4, make_float4(o[4], o[5], o[6], o[7]));
        if (lane == 0) atomicAdd(&g_cnt[b], 1.0f);
    } else {
        __half h[8];
#pragma unroll
        for (int j = 0; j < 8; j++) h[j] = __float2half(o[j]);
        *(uint4*)(g_xh + (size_t)d * DM + lane * 8) = *(uint4*)h;
    }
}

// ---------------- GRU + FC ----------------
__global__ void gru_fc(const float* __restrict__ W_ih, const float* __restrict__ b_ih,
                       const float* __restrict__ b_hh,
                       const float* __restrict__ W_fc, const float* __restrict__ b_fc,
                       float* __restrict__ out)
{
    __shared__ float gsh[256];
    __shared__ float gish[192];
    __shared__ float hsh[64];
    int b = blockIdx.x;
    int t = threadIdx.x;
    float inv = 1.0f / fmaxf(g_cnt[b], 1.0f);
    gsh[t] = g_pool[b * DM + t] * inv;
    __syncthreads();
    if (t < 192) {
        float s = b_ih[t];
        const float* w = W_ih + t * 256;
#pragma unroll 8
        for (int k = 0; k < 256; k++) s += gsh[k] * w[k];
        gish[t] = s;
    }
    __syncthreads();
    if (t < 64) {
        float r = 1.f / (1.f + expf(-(gish[t] + b_hh[t])));
        float z = 1.f / (1.f + expf(-(gish[64 + t] + b_hh[64 + t])));
        float n = tanhf(gish[128 + t] + r * b_hh[128 + t]);
        hsh[t] = (1.f - z) * n;
    }
    __syncthreads();
    if (t < 2) {
        float s = b_fc[t];
        const float* w = W_fc + t * 64;
#pragma unroll
        for (int k = 0; k < 64; k++) s += hsh[k] * w[k];
        out[b * 2 + t] = s;
    }
}

// ---------------- launch ----------------
extern "C" void kernel_launch(void* const* d_in, const int* in_sizes, int n_in,
                              void* d_out, int out_size)
{
    const float* x     = (const float*)d_in[0];
    const int*   eidx  = (const int*)d_in[1];
    const int*   batch = (const int*)d_in[2];
    const int*   etid  = (const int*)d_in[3];
    const float* Wq    = (const float*)d_in[4];
    const float* bq    = (const float*)d_in[5];
    const float* Wk    = (const float*)d_in[6];
    const float* bk    = (const float*)d_in[7];
    const float* Wv    = (const float*)d_in[8];
    const float* bv    = (const float*)d_in[9];
    const float* Ee    = (const float*)d_in[10];
    const float* W_ih  = (const float*)d_in[11];
    const float* b_ih  = (const float*)d_in[12];
    const float* b_hh  = (const float*)d_in[14];
    const float* W_fc  = (const float*)d_in[15];
    const float* b_fc  = (const float*)d_in[16];

    const int* src = eidx;
    const int* dst = eidx + N_EDGES;

    static int smem_set = 0;
    const int gemm_smem = 4 * STAGE_E * (int)sizeof(__half);   // 75776 B
    if (!smem_set) {
        cudaFuncSetAttribute(gemm_qkv_mma, cudaFuncAttributeMaxDynamicSharedMemorySize, gemm_smem);
        smem_set = 1;
    }

    convert_w_kernel<<<(NLAYER * DM * QKVW + 255) / 256, 256>>>(Wq, Wk, Wv);
    convert_x_kernel<<<(N_PAD * 64 + 255) / 256, 256>>>(x);   // also zeroes deg/pool/cnt

    hist_kernel<<<(N_EDGES + 255) / 256, 256>>>(dst);
    scan1_kernel<<<SCAN_B, 1024>>>();
    scan2_kernel<<<1, 32>>>();
    scan3_kernel<<<(N_NODES + 255) / 256, 256>>>();
    scatter_kernel<<<(N_EDGES + 255) / 256, 256>>>(src, dst, etid);

    dim3 ggrid(N_PAD / 128, 6);
    for (int l = 0; l < NLAYER; l++) {
        gemm_qkv_mma<<<ggrid, 256, gemm_smem>>>(l, bq + l * DM, bk + l * DM, bv + l * DM);
        attn_kernel<<<(N_NODES * 32 + 255) / 256, 256>>>(Ee + l * 8 * DM, batch,
                                                         l == NLAYER - 1 ? 1 : 0);
    }
    gru_fc<<<NGRAPH, 256>>>(W_ih, b_ih, b_hh, W_fc, b_fc, (float*)d_out);
}